// round 2
// baseline (speedup 1.0000x reference)
#include <cuda_runtime.h>

typedef unsigned long long ull;

#define MAXB 4096

static __device__ float g_x2[MAXB];
static __device__ float g_xinv[MAXB];
static __device__ float g_y2[MAXB];
static __device__ float g_yinv[MAXB];
static __device__ float g_pos[MAXB];
static __device__ float g_part[32 * MAXB];   // per-column-tile partial row sums

__device__ __forceinline__ void fma2(ull& d, ull a, ull b) {
    asm("fma.rn.f32x2 %0, %1, %2, %0;" : "+l"(d) : "l"(a), "l"(b));
}

__device__ __forceinline__ ull dup2(float v) {
    ull r;
    asm("mov.b64 %0, {%1, %1};" : "=l"(r) : "r"(__float_as_uint(v)));
    return r;
}

// ---------------- Kernel 1: per-row squared norms + inverse norms ----------------
__global__ void hyp_norms(const float* __restrict__ z, const float* __restrict__ zp) {
    int row = blockIdx.x;
    int t = threadIdx.x;                 // 128 threads = D
    float a = z[row * 128 + t];
    float b = zp[row * 128 + t];
    float sa = a * a, sb = b * b;
    #pragma unroll
    for (int o = 16; o; o >>= 1) {
        sa += __shfl_xor_sync(0xffffffffu, sa, o);
        sb += __shfl_xor_sync(0xffffffffu, sb, o);
    }
    __shared__ float ra[4], rb[4];
    if ((t & 31) == 0) { ra[t >> 5] = sa; rb[t >> 5] = sb; }
    __syncthreads();
    if (t == 0) {
        float x2 = ra[0] + ra[1] + ra[2] + ra[3];
        float y2 = rb[0] + rb[1] + rb[2] + rb[3];
        g_x2[row] = x2;
        g_y2[row] = y2;
        g_xinv[row] = rsqrtf(fmaxf(x2, 1e-24f));   // == 1/max(norm,1e-12)
        g_yinv[row] = rsqrtf(fmaxf(y2, 1e-24f));
    }
}

// ---------------- Kernel 2: pairwise GEMM + hyperbolic epilogue ----------------
// Tile: 64 rows (i) x 128 cols (j), 256 threads = 8 warps.
// Warp w owns rows w*8..w*8+7 (4 packed pairs); lane l owns cols {l, l+32, l+64, l+96}.
// A in smem: transposed [k][64], XOR-swizzled (even xor -> LDS.64 pair order preserved).
// B in smem: transposed + duplicated [k][128] ulls, XOR-swizzled; LDS.64 -> (b,b).
__global__ void __launch_bounds__(256, 1)
hyp_pair(const float* __restrict__ z, const float* __restrict__ zp) {
    extern __shared__ float smem_f[];
    float* As = smem_f;                          // 128*64 floats  = 32 KB
    ull*   Bs = (ull*)(smem_f + 128 * 64);       // 128*128 ulls   = 128 KB

    const int tid  = threadIdx.x;
    const int lane = tid & 31;
    const int warp = tid >> 5;
    const int row0 = blockIdx.y * 64;
    const int col0 = blockIdx.x * 128;

    // ---- fill A (coalesced LDG, swizzled transpose store) ----
    {
        const float4* zA = (const float4*)z + row0 * 32;
        #pragma unroll
        for (int p = 0; p < 8; p++) {
            int idx = p * 256 + tid;
            int kq = idx & 31;        // lanes sweep k -> coalesced 512B rows
            int r  = idx >> 5;
            float4 v = zA[r * 32 + kq];
            int h = (2 * kq) & 30;    // even XOR swizzle
            As[(kq * 4 + 0) * 64 + (r ^ h)] = v.x;
            As[(kq * 4 + 1) * 64 + (r ^ h)] = v.y;
            As[(kq * 4 + 2) * 64 + (r ^ h)] = v.z;
            As[(kq * 4 + 3) * 64 + (r ^ h)] = v.w;
        }
    }
    // ---- fill B (coalesced LDG, duplicated + swizzled transpose store) ----
    {
        const float4* zB = (const float4*)zp + col0 * 32;
        #pragma unroll
        for (int p = 0; p < 16; p++) {
            int idx = p * 256 + tid;
            int kq = idx & 31;
            int cj = idx >> 5;
            float4 v = zB[cj * 32 + kq];
            int g = kq & 15;
            Bs[(kq * 4 + 0) * 128 + (cj ^ g)] = dup2(v.x);
            Bs[(kq * 4 + 1) * 128 + (cj ^ g)] = dup2(v.y);
            Bs[(kq * 4 + 2) * 128 + (cj ^ g)] = dup2(v.z);
            Bs[(kq * 4 + 3) * 128 + (cj ^ g)] = dup2(v.w);
        }
    }
    __syncthreads();

    ull acc[4][4];
    #pragma unroll
    for (int i = 0; i < 4; i++)
        #pragma unroll
        for (int j = 0; j < 4; j++) acc[i][j] = 0ull;

    const int rb = warp * 8;
    #pragma unroll 2
    for (int kq = 0; kq < 32; kq++) {
        const int h  = (2 * kq) & 30;
        const int lg = lane ^ (kq & 15);
        #pragma unroll
        for (int s = 0; s < 4; s++) {
            const float* arow = As + (kq * 4 + s) * 64;
            const ull*   brow = Bs + (kq * 4 + s) * 128;
            ull a0 = *(const ull*)(arow + ((rb + 0) ^ h));   // rows rb, rb+1 packed
            ull a1 = *(const ull*)(arow + ((rb + 2) ^ h));
            ull a2 = *(const ull*)(arow + ((rb + 4) ^ h));
            ull a3 = *(const ull*)(arow + ((rb + 6) ^ h));
            ull b0 = brow[lg];
            ull b1 = brow[lg + 32];
            ull b2 = brow[lg + 64];
            ull b3 = brow[lg + 96];
            fma2(acc[0][0], a0, b0); fma2(acc[0][1], a0, b1);
            fma2(acc[0][2], a0, b2); fma2(acc[0][3], a0, b3);
            fma2(acc[1][0], a1, b0); fma2(acc[1][1], a1, b1);
            fma2(acc[1][2], a1, b2); fma2(acc[1][3], a1, b3);
            fma2(acc[2][0], a2, b0); fma2(acc[2][1], a2, b1);
            fma2(acc[2][2], a2, b2); fma2(acc[2][3], a2, b3);
            fma2(acc[3][0], a3, b0); fma2(acc[3][1], a3, b1);
            fma2(acc[3][2], a3, b2); fma2(acc[3][3], a3, b3);
        }
    }

    // ---- epilogue: hyperbolic distance + angle sim + exp row-sums ----
    float y2v[4], yiv[4];
    #pragma unroll
    for (int c = 0; c < 4; c++) {
        int gj = col0 + lane + 32 * c;
        y2v[c] = g_y2[gj];
        yiv[c] = g_yinv[gj];
    }
    const float Cc = 0.05f;
    const float SQC = 0.22360679775f;          // sqrt(c)
    #pragma unroll
    for (int rp = 0; rp < 4; rp++) {
        float dv[2][4];
        #pragma unroll
        for (int c = 0; c < 4; c++) {
            unsigned lo, hi;
            asm("mov.b64 {%0, %1}, %2;" : "=r"(lo), "=r"(hi) : "l"(acc[rp][c]));
            dv[0][c] = __uint_as_float(lo);
            dv[1][c] = __uint_as_float(hi);
        }
        #pragma unroll
        for (int hh = 0; hh < 2; hh++) {
            int gi = row0 + rb + rp * 2 + hh;
            float x2  = g_x2[gi];
            float xin = g_xinv[gi];
            float B1 = 1.0f - Cc * x2;
            float s = 0.0f;
            #pragma unroll
            for (int c = 0; c < 4; c++) {
                int gj = col0 + lane + 32 * c;
                float d  = dv[hh][c];                 // <z_i, z'_j>
                float y2 = y2v[c];
                float A1  = 1.0f + Cc * (y2 - 2.0f * d);
                float den = fmaxf(1.0f - 2.0f * Cc * d + Cc * Cc * x2 * y2, 1e-6f);
                float num = fmaxf(A1 * A1 * x2 - 2.0f * A1 * B1 * d + B1 * B1 * y2, 0.0f);
                float mn  = num * rsqrtf(fmaxf(num, 1e-37f));     // sqrt(num)
                float u   = fminf(__fdividef(SQC * mn, den), 1.0f - 1e-6f);
                float lgr = __logf(__fdividef(1.0f + u, 1.0f - u)); // 2*atanh(u)
                float cosv = d * xin * yiv[c];
                // combined = 0.5*(-dist/T) + 0.5*cos/T ; dist = (1/sqrt(c))*lgr
                float comb = 5.0f * cosv - 22.360679775f * lgr;
                if (gi == gj) g_pos[gi] = comb;       // diagonal -> pos_sim
                else          s += __expf(comb);      // off-diagonal -> denom
            }
            #pragma unroll
            for (int o = 16; o; o >>= 1) s += __shfl_xor_sync(0xffffffffu, s, o);
            if (lane == 0) g_part[blockIdx.x * MAXB + gi] = s;   // deterministic partials
        }
    }
}

// ---------------- Kernel 3: final reduction to the scalar loss ----------------
__global__ void hyp_finish(float* __restrict__ out, int B, int nparts) {
    int t = threadIdx.x;   // 256
    float s = 0.0f;
    for (int i = t; i < B; i += 256) {
        float dsum = 0.0f;
        for (int p = 0; p < nparts; p++) dsum += g_part[p * MAXB + i];
        s += __logf(dsum) - g_pos[i];
    }
    #pragma unroll
    for (int o = 16; o; o >>= 1) s += __shfl_xor_sync(0xffffffffu, s, o);
    __shared__ float red[8];
    if ((t & 31) == 0) red[t >> 5] = s;
    __syncthreads();
    if (t == 0) {
        float tot = 0.0f;
        #pragma unroll
        for (int w = 0; w < 8; w++) tot += red[w];
        out[0] = tot / (float)B;
    }
}

extern "C" void kernel_launch(void* const* d_in, const int* in_sizes, int n_in,
                              void* d_out, int out_size) {
    (void)n_in; (void)out_size;
    const float* z  = (const float*)d_in[0];
    const float* zp = (const float*)d_in[1];
    int B = in_sizes[0] / 128;

    hyp_norms<<<B, 128>>>(z, zp);

    int smem = 128 * 64 * (int)sizeof(float) + 128 * 128 * (int)sizeof(ull); // 160 KB
    cudaFuncSetAttribute(hyp_pair, cudaFuncAttributeMaxDynamicSharedMemorySize, smem);
    dim3 grid(B / 128, B / 64);
    hyp_pair<<<grid, 256, smem>>>(z, zp);

    hyp_finish<<<1, 256>>>((float*)d_out, B, B / 128);
}

// round 3
// speedup vs baseline: 1.1113x; 1.1113x over previous
#include <cuda_runtime.h>

typedef unsigned long long ull;

#define MAXB 4096

static __device__ float g_pos[MAXB];
static __device__ float g_part[32 * MAXB];   // [col-tile][row] partial row sums
static __device__ unsigned g_done = 0;

__device__ __forceinline__ void fma2(ull& d, ull a, ull b) {
    asm("fma.rn.f32x2 %0, %1, %2, %0;" : "+l"(d) : "l"(a), "l"(b));
}

__device__ __forceinline__ ull dup2(float v) {
    ull r;
    asm("mov.b64 %0, {%1, %1};" : "=l"(r) : "r"(__float_as_uint(v)));
    return r;
}

// ---------------- Fused kernel: GEMM + hyperbolic epilogue + norms + final loss ----------------
// Tile: 64 rows (i) x 128 cols (j), 256 threads = 8 warps.
// Warp w owns rows w*8..w*8+7 (4 packed pairs); lane l owns cols {l, l+32, l+64, l+96}.
// A in smem: transposed [k][64], XOR-swizzled (even xor -> LDS.64 pair order preserved).
// B in smem: transposed + duplicated [k][128] ulls, XOR-swizzled; LDS.64 -> (b,b).
// Row/col squared norms computed during the fills via warp shuffle (each warp
// loads one full row per fill iteration).
__global__ void __launch_bounds__(256, 1)
hyp_pair(const float* __restrict__ z, const float* __restrict__ zp,
         float* __restrict__ out, int B) {
    extern __shared__ float smem_f[];
    float* As  = smem_f;                          // 128*64 floats  = 32 KB
    ull*   Bs  = (ull*)(smem_f + 128 * 64);       // 128*128 ulls   = 128 KB
    float* sx2 = (float*)(Bs + 128 * 128);        // 64 floats
    float* sy2 = sx2 + 64;                        // 128 floats

    const int tid  = threadIdx.x;
    const int lane = tid & 31;
    const int warp = tid >> 5;
    const int row0 = blockIdx.y * 64;
    const int col0 = blockIdx.x * 128;

    // ---- fill A (coalesced LDG, swizzled transpose store, fused row-norm) ----
    {
        const float4* zA = (const float4*)z + row0 * 32;
        #pragma unroll
        for (int p = 0; p < 8; p++) {
            int r  = p * 8 + warp;      // warp handles one full row; lanes sweep k
            int kq = lane;
            float4 v = zA[r * 32 + kq];
            int h = (2 * kq) & 30;      // even XOR swizzle
            As[(kq * 4 + 0) * 64 + (r ^ h)] = v.x;
            As[(kq * 4 + 1) * 64 + (r ^ h)] = v.y;
            As[(kq * 4 + 2) * 64 + (r ^ h)] = v.z;
            As[(kq * 4 + 3) * 64 + (r ^ h)] = v.w;
            float s = v.x * v.x + v.y * v.y + v.z * v.z + v.w * v.w;
            #pragma unroll
            for (int o = 16; o; o >>= 1) s += __shfl_xor_sync(0xffffffffu, s, o);
            if (lane == 0) sx2[r] = s;
        }
    }
    // ---- fill B (coalesced LDG, duplicated + swizzled transpose store, fused col-norm) ----
    {
        const float4* zB = (const float4*)zp + col0 * 32;
        #pragma unroll
        for (int p = 0; p < 16; p++) {
            int cj = p * 8 + warp;
            int kq = lane;
            float4 v = zB[cj * 32 + kq];
            int g = kq & 15;
            Bs[(kq * 4 + 0) * 128 + (cj ^ g)] = dup2(v.x);
            Bs[(kq * 4 + 1) * 128 + (cj ^ g)] = dup2(v.y);
            Bs[(kq * 4 + 2) * 128 + (cj ^ g)] = dup2(v.z);
            Bs[(kq * 4 + 3) * 128 + (cj ^ g)] = dup2(v.w);
            float s = v.x * v.x + v.y * v.y + v.z * v.z + v.w * v.w;
            #pragma unroll
            for (int o = 16; o; o >>= 1) s += __shfl_xor_sync(0xffffffffu, s, o);
            if (lane == 0) sy2[cj] = s;
        }
    }
    __syncthreads();

    ull acc[4][4];
    #pragma unroll
    for (int i = 0; i < 4; i++)
        #pragma unroll
        for (int j = 0; j < 4; j++) acc[i][j] = 0ull;

    const int rb = warp * 8;
    #pragma unroll 2
    for (int kq = 0; kq < 32; kq++) {
        const int h  = (2 * kq) & 30;
        const int lg = lane ^ (kq & 15);
        #pragma unroll
        for (int s = 0; s < 4; s++) {
            const float* arow = As + (kq * 4 + s) * 64;
            const ull*   brow = Bs + (kq * 4 + s) * 128;
            ull a0 = *(const ull*)(arow + ((rb + 0) ^ h));   // rows rb, rb+1 packed
            ull a1 = *(const ull*)(arow + ((rb + 2) ^ h));
            ull a2 = *(const ull*)(arow + ((rb + 4) ^ h));
            ull a3 = *(const ull*)(arow + ((rb + 6) ^ h));
            ull b0 = brow[lg];
            ull b1 = brow[lg + 32];
            ull b2 = brow[lg + 64];
            ull b3 = brow[lg + 96];
            fma2(acc[0][0], a0, b0); fma2(acc[0][1], a0, b1);
            fma2(acc[0][2], a0, b2); fma2(acc[0][3], a0, b3);
            fma2(acc[1][0], a1, b0); fma2(acc[1][1], a1, b1);
            fma2(acc[1][2], a1, b2); fma2(acc[1][3], a1, b3);
            fma2(acc[2][0], a2, b0); fma2(acc[2][1], a2, b1);
            fma2(acc[2][2], a2, b2); fma2(acc[2][3], a2, b3);
            fma2(acc[3][0], a3, b0); fma2(acc[3][1], a3, b1);
            fma2(acc[3][2], a3, b2); fma2(acc[3][3], a3, b3);
        }
    }

    // ---- epilogue: hyperbolic distance + angle sim + exp row-sums ----
    float y2v[4], yiv[4];
    #pragma unroll
    for (int c = 0; c < 4; c++) {
        float y2 = sy2[lane + 32 * c];
        y2v[c] = y2;
        yiv[c] = rsqrtf(fmaxf(y2, 1e-24f));     // == 1/max(norm,1e-12)
    }
    const float Cc = 0.05f;
    const float SQC = 0.22360679775f;          // sqrt(c)
    #pragma unroll
    for (int rp = 0; rp < 4; rp++) {
        float dv[2][4];
        #pragma unroll
        for (int c = 0; c < 4; c++) {
            unsigned lo, hi;
            asm("mov.b64 {%0, %1}, %2;" : "=r"(lo), "=r"(hi) : "l"(acc[rp][c]));
            dv[0][c] = __uint_as_float(lo);
            dv[1][c] = __uint_as_float(hi);
        }
        #pragma unroll
        for (int hh = 0; hh < 2; hh++) {
            int li = rb + rp * 2 + hh;
            int gi = row0 + li;
            float x2  = sx2[li];
            float xin = rsqrtf(fmaxf(x2, 1e-24f));
            float B1 = 1.0f - Cc * x2;
            float s = 0.0f;
            #pragma unroll
            for (int c = 0; c < 4; c++) {
                int gj = col0 + lane + 32 * c;
                float d  = dv[hh][c];                 // <z_i, z'_j>
                float y2 = y2v[c];
                float A1  = 1.0f + Cc * (y2 - 2.0f * d);
                float den = fmaxf(1.0f - 2.0f * Cc * d + Cc * Cc * x2 * y2, 1e-6f);
                float num = fmaxf(A1 * A1 * x2 - 2.0f * A1 * B1 * d + B1 * B1 * y2, 0.0f);
                float mn  = num * rsqrtf(fmaxf(num, 1e-37f));     // sqrt(num)
                float u   = fminf(__fdividef(SQC * mn, den), 1.0f - 1e-6f);
                float lgr = __logf(__fdividef(1.0f + u, 1.0f - u)); // 2*atanh(u)
                float cosv = d * xin * yiv[c];
                // combined = 0.5*(-dist/T) + 0.5*cos/T ; dist = (1/sqrt(c))*lgr
                float comb = 5.0f * cosv - 22.360679775f * lgr;
                if (gi == gj) g_pos[gi] = comb;       // diagonal -> pos_sim
                else          s += __expf(comb);      // off-diagonal -> denom
            }
            #pragma unroll
            for (int o = 16; o; o >>= 1) s += __shfl_xor_sync(0xffffffffu, s, o);
            if (lane == 0) g_part[blockIdx.x * MAXB + gi] = s;   // deterministic partials
        }
    }

    // ---- last CTA to finish performs the final reduction (deterministic) ----
    __shared__ unsigned s_rank;
    __syncthreads();
    __threadfence();
    if (tid == 0) s_rank = atomicAdd(&g_done, 1u);
    __syncthreads();
    unsigned nblk = gridDim.x * gridDim.y;
    if (s_rank == nblk - 1) {
        int nparts = gridDim.x;
        float s = 0.0f;
        for (int i = tid; i < B; i += 256) {
            float dsum = 0.0f;
            for (int p = 0; p < nparts; p++) dsum += g_part[p * MAXB + i];
            s += __logf(dsum) - g_pos[i];
        }
        #pragma unroll
        for (int o = 16; o; o >>= 1) s += __shfl_xor_sync(0xffffffffu, s, o);
        __shared__ float red[8];
        if (lane == 0) red[warp] = s;
        __syncthreads();
        if (tid == 0) {
            float tot = 0.0f;
            #pragma unroll
            for (int w = 0; w < 8; w++) tot += red[w];
            out[0] = tot / (float)B;
            g_done = 0;                         // reset for next replay
        }
    }
}

extern "C" void kernel_launch(void* const* d_in, const int* in_sizes, int n_in,
                              void* d_out, int out_size) {
    (void)n_in; (void)out_size;
    const float* z  = (const float*)d_in[0];
    const float* zp = (const float*)d_in[1];
    int B = in_sizes[0] / 128;

    int smem = 128 * 64 * (int)sizeof(float) + 128 * 128 * (int)sizeof(ull)
             + 192 * (int)sizeof(float);                       // ~160.75 KB
    cudaFuncSetAttribute(hyp_pair, cudaFuncAttributeMaxDynamicSharedMemorySize, smem);
    dim3 grid(B / 128, B / 64);
    hyp_pair<<<grid, 256, smem>>>(z, zp, (float*)d_out, B);
}